// round 15
// baseline (speedup 1.0000x reference)
#include <cuda_runtime.h>
#include <cuda_bf16.h>
#include <cstdint>

#define D        128
#define MAX_N    50000
#define MAX_E    800000
#define TILE_M   128
#define THREADS  256
#define ASTRIDE  136          // padded bf16 stride: rows 4 banks apart
#define SCAN_B   1024         // scan block size

__device__ int   g_idx_is64;

// Incidence-CSR scratch
__device__ int  g_off[MAX_N + 1];
__device__ int  g_cur[MAX_N];
__device__ int  g_tmp[MAX_N];
__device__ int  g_bsum[64];
__device__ int2 g_ent[2 * MAX_E];     // (other_node, weight_bits | flag<<31)

// Pre-split, pre-transposed weights: 6 chunks of [n=128][k=128] bf16.
__device__ uint4 g_wt_hi[6 * 128 * 128 / 8];
__device__ uint4 g_wt_lo[6 * 128 * 128 / 8];

// ---------------------------------------------------------------------------
__device__ __forceinline__ void split_bf16(float f, uint16_t& h, uint16_t& l) {
    __nv_bfloat16 hi = __float2bfloat16_rn(f);
    __nv_bfloat16 lo = __float2bfloat16_rn(f - __bfloat162float(hi));
    h = __bfloat16_as_ushort(hi);
    l = __bfloat16_as_ushort(lo);
}

__device__ __forceinline__ void mma16816(float c[4], const uint32_t a[4],
                                         const uint32_t b[2]) {
    asm volatile(
        "mma.sync.aligned.m16n8k16.row.col.f32.bf16.bf16.f32 "
        "{%0,%1,%2,%3}, {%4,%5,%6,%7}, {%8,%9}, {%0,%1,%2,%3};"
        : "+f"(c[0]), "+f"(c[1]), "+f"(c[2]), "+f"(c[3])
        : "r"(a[0]), "r"(a[1]), "r"(a[2]), "r"(a[3]), "r"(b[0]), "r"(b[1]));
}

__device__ __forceinline__ void ldsm_x4(uint32_t& r0, uint32_t& r1,
                                        uint32_t& r2, uint32_t& r3,
                                        uint32_t addr) {
    asm volatile("ldmatrix.sync.aligned.m8n8.x4.shared.b16 {%0,%1,%2,%3}, [%4];"
                 : "=r"(r0), "=r"(r1), "=r"(r2), "=r"(r3) : "r"(addr));
}

__device__ __forceinline__ uint32_t smem_u32(const void* p) {
    uint32_t a;
    asm("{ .reg .u64 t; cvta.to.shared.u64 t, %1; cvt.u32.u64 %0, t; }"
        : "=r"(a) : "l"(p));
    return a;
}

__device__ __forceinline__ void load_edge(const void* eidx, int E, int N,
                                          int e, int& src, int& dst) {
    if (g_idx_is64) {
        const long long* p = (const long long*)eidx;
        src = (int)p[e];
        dst = (int)p[(size_t)E + e];
    } else {
        const int* p = (const int*)eidx;
        src = p[e];
        dst = p[(size_t)E + e];
    }
    src = min(max(src, 0), N - 1);
    dst = min(max(dst, 0), N - 1);
}

// ===========================================================================
// Kernel 0: detect edge_index dtype
// ===========================================================================
__global__ void detect_idx_kernel(const void* __restrict__ eidx, int E, int N) {
    if (threadIdx.x != 0 || blockIdx.x != 0) return;
    const long long* p64 = (const long long*)eidx;
    int stride = E / 64; if (stride < 1) stride = 1;
    int ok = 1;
    for (int i = 0; i < 64; ++i) {
        long long v = p64[(long long)i * stride];
        if (v < 0 || v >= N) { ok = 0; break; }
    }
    g_idx_is64 = ok;
}

// ===========================================================================
// CSR build: zero-deg -> histogram -> 3-phase scan -> fill
// ===========================================================================
__global__ void zero_deg_kernel(int N) {
    int i = blockIdx.x * blockDim.x + threadIdx.x;
    if (i < N) g_off[i] = 0;
}

__global__ void hist_kernel(const void* __restrict__ eidx, int E, int N) {
    int e = blockIdx.x * blockDim.x + threadIdx.x;
    if (e >= E) return;
    int src, dst;
    load_edge(eidx, E, N, e, src, dst);
    atomicAdd(&g_off[dst], 1);
    atomicAdd(&g_off[src], 1);
}

__global__ void scan_block_kernel(int N) {
    __shared__ int wsum[32];
    int i    = blockIdx.x * SCAN_B + threadIdx.x;
    int lane = threadIdx.x & 31;
    int w    = threadIdx.x >> 5;

    int v = (i < N) ? g_off[i] : 0;
    int incl = v;
    #pragma unroll
    for (int d = 1; d < 32; d <<= 1) {
        int t = __shfl_up_sync(0xffffffff, incl, d);
        if (lane >= d) incl += t;
    }
    if (lane == 31) wsum[w] = incl;
    __syncthreads();
    if (w == 0) {
        int s = wsum[lane];
        #pragma unroll
        for (int d = 1; d < 32; d <<= 1) {
            int t = __shfl_up_sync(0xffffffff, s, d);
            if (lane >= d) s += t;
        }
        wsum[lane] = s;
    }
    __syncthreads();
    int wo = (w > 0) ? wsum[w - 1] : 0;
    if (i < N) g_tmp[i] = incl - v + wo;
    if (threadIdx.x == SCAN_B - 1) g_bsum[blockIdx.x] = wsum[31];
}

__global__ void scan_tops_kernel(int nblk) {
    __shared__ int s[64];
    int t = threadIdx.x;
    s[t] = (t < nblk) ? g_bsum[t] : 0;
    __syncthreads();
    #pragma unroll
    for (int d = 1; d < 64; d <<= 1) {
        int v = (t >= d) ? s[t - d] : 0;
        __syncthreads();
        s[t] += v;
        __syncthreads();
    }
    g_bsum[t] = s[t];
}

__global__ void scan_add_kernel(int N) {
    int i = blockIdx.x * SCAN_B + threadIdx.x;
    if (i < N) {
        int base = (blockIdx.x > 0) ? g_bsum[blockIdx.x - 1] : 0;
        int v = g_tmp[i] + base;
        g_off[i] = v;
        g_cur[i] = v;
    }
    if (i == 0) g_off[N] = g_bsum[(N + SCAN_B - 1) / SCAN_B - 1];
}

__global__ void fill_kernel(const void* __restrict__ eidx,
                            const float* __restrict__ ew, int E, int N) {
    int e = blockIdx.x * blockDim.x + threadIdx.x;
    if (e >= E) return;
    int src, dst;
    load_edge(eidx, E, N, e, src, dst);
    int wbits = __float_as_int(__ldg(&ew[e]));
    int p1 = atomicAdd(&g_cur[dst], 1);
    g_ent[p1] = make_int2(src, wbits);                    // mi[dst] += w*x[src]
    int p2 = atomicAdd(&g_cur[src], 1);
    g_ent[p2] = make_int2(dst, wbits | (int)0x80000000);  // mo[src] += w*x[dst]
}

// ===========================================================================
// Kernel P: pre-split + transpose weights into g_wt_hi/lo [chunk][n][k]
// ===========================================================================
__global__ void prep_w_kernel(const float* __restrict__ W1,
                              const float* __restrict__ W2,
                              const float* __restrict__ W3,
                              const float* __restrict__ W4) {
    int id = blockIdx.x * blockDim.x + threadIdx.x;
    if (id >= 6 * 128 * 128) return;
    int c = id >> 14;
    int n = (id >> 7) & 127;
    int k = id & 127;
    const float* src = (c < 3) ? (W1 + (size_t)c * 128 * 128)
                     : (c == 3) ? W2 : (c == 4) ? W3 : W4;
    float w = src[(size_t)k * 128 + n];               // W[k][n] -> B[n][k]
    uint16_t h, l;
    split_bf16(w, h, l);
    reinterpret_cast<uint16_t*>(g_wt_hi)[id] = h;
    reinterpret_cast<uint16_t*>(g_wt_lo)[id] = l;
}

// ===========================================================================
// Fused kernel: in-block CSR aggregation + 4-layer mma.sync bf16-split MLP.
//   smem regions (each 128*ASTRIDE bf16 = 34816 B):
//     A_HI/A_LO   : mi tile, later x tile, later activations
//     A2_HI/A2_LO : mo tile
//     B_HI/B_LO   : weight tile (also fp32 out staging at the end)
// ===========================================================================
#define RB        (128 * ASTRIDE * 2)
#define OFF_A_HI  0
#define OFF_A_LO  (OFF_A_HI  + RB)
#define OFF_A2_HI (OFF_A_LO  + RB)
#define OFF_A2_LO (OFF_A2_HI + RB)
#define OFF_B_HI  (OFF_A2_LO + RB)
#define OFF_B_LO  (OFF_B_HI  + RB)
#define SMEM_TOTAL (OFF_B_LO + RB)        // 208896 B
#define ROWB      (ASTRIDE * 2)           // 272 bytes per tile row

__global__ void __launch_bounds__(THREADS, 1)
fused_kernel(const float* __restrict__ x,
             const float* __restrict__ b1, const float* __restrict__ b2,
             const float* __restrict__ b3, const float* __restrict__ b4,
             float* __restrict__ out, int N) {
    extern __shared__ char smem[];
    uint16_t* sAh  = reinterpret_cast<uint16_t*>(smem + OFF_A_HI);
    uint16_t* sAl  = reinterpret_cast<uint16_t*>(smem + OFF_A_LO);
    uint16_t* sA2h = reinterpret_cast<uint16_t*>(smem + OFF_A2_HI);
    uint16_t* sA2l = reinterpret_cast<uint16_t*>(smem + OFF_A2_LO);
    uint16_t* sBh  = reinterpret_cast<uint16_t*>(smem + OFF_B_HI);
    uint16_t* sBl  = reinterpret_cast<uint16_t*>(smem + OFF_B_LO);
    const uint32_t sbase = smem_u32(smem);

    const int tid  = threadIdx.x;
    const int wid  = tid >> 5;
    const int lane = tid & 31;
    const int gid  = lane >> 2;
    const int t4   = lane & 3;
    const int wr0  = (wid & 3) * 32;
    const int wn0  = (wid >> 2) * 64;
    const int r0   = blockIdx.x * TILE_M;

    // ldmatrix per-lane source rows (within a tile region)
    const int a_row = wr0 + (lane & 7) + ((lane >> 3) & 1) * 8;
    const int a_kof = ((lane >> 4) & 1) * 8;
    const int b_row = wn0 + (lane & 7) + ((lane >> 4) & 1) * 8;
    const int b_kof = ((lane >> 3) & 1) * 8;
    const uint32_t aRowOff = (uint32_t)(a_row * ROWB + a_kof * 2);
    const uint32_t bBaseH  = sbase + OFF_B_HI + (uint32_t)(b_row * ROWB + b_kof * 2);
    const uint32_t bBaseL  = sbase + OFF_B_LO + (uint32_t)(b_row * ROWB + b_kof * 2);

    float c[2][8][4];

    // ---- phase 1: CSR aggregation directly into split-bf16 A / A2 tiles ---
    auto gather = [&]() {
        #pragma unroll 1
        for (int i = 0; i < 16; ++i) {
            int li = wid * 16 + i;          // local tile row
            int n  = r0 + li;
            float4 mi = make_float4(0.f, 0.f, 0.f, 0.f);
            float4 mo = make_float4(0.f, 0.f, 0.f, 0.f);
            if (n < N) {
                int s = g_off[n];
                int t = g_off[n + 1];
                int j = s;
                int g = min(8, t - j);
                int2 ecur = make_int2(0, 0);
                if (g > 0) ecur = __ldg(&g_ent[j + min(lane & 7, g - 1)]);
                while (j < t) {
                    int jn = j + g;
                    int gn = min(8, t - jn);
                    int2 enext = make_int2(0, 0);
                    if (gn > 0) enext = __ldg(&g_ent[jn + min(lane & 7, gn - 1)]);
                    #pragma unroll
                    for (int u = 0; u < 8; ++u) {
                        int ox = __shfl_sync(0xffffffffu, ecur.x, u);
                        int ob = __shfl_sync(0xffffffffu, ecur.y, u);
                        if (u < g) {                    // warp-uniform
                            float w = __int_as_float(ob & 0x7fffffff);
                            float4 v = __ldg(reinterpret_cast<const float4*>(
                                                 x + (size_t)ox * D) + lane);
                            if (ob < 0) {
                                mo.x = fmaf(w, v.x, mo.x); mo.y = fmaf(w, v.y, mo.y);
                                mo.z = fmaf(w, v.z, mo.z); mo.w = fmaf(w, v.w, mo.w);
                            } else {
                                mi.x = fmaf(w, v.x, mi.x); mi.y = fmaf(w, v.y, mi.y);
                                mi.z = fmaf(w, v.z, mi.z); mi.w = fmaf(w, v.w, mi.w);
                            }
                        }
                    }
                    ecur = enext;
                    j = jn;
                    g = gn;
                }
            }
            // split + store: mi -> A, mo -> A2 (uint2 = 4 bf16 at col lane*4)
            uint16_t h0,h1,h2,h3, l0,l1,l2,l3;
            int o = li * ASTRIDE + lane * 4;
            split_bf16(mi.x, h0, l0); split_bf16(mi.y, h1, l1);
            split_bf16(mi.z, h2, l2); split_bf16(mi.w, h3, l3);
            *reinterpret_cast<uint2*>(sAh + o) =
                make_uint2((uint32_t)h0 | ((uint32_t)h1 << 16),
                           (uint32_t)h2 | ((uint32_t)h3 << 16));
            *reinterpret_cast<uint2*>(sAl + o) =
                make_uint2((uint32_t)l0 | ((uint32_t)l1 << 16),
                           (uint32_t)l2 | ((uint32_t)l3 << 16));
            split_bf16(mo.x, h0, l0); split_bf16(mo.y, h1, l1);
            split_bf16(mo.z, h2, l2); split_bf16(mo.w, h3, l3);
            *reinterpret_cast<uint2*>(sA2h + o) =
                make_uint2((uint32_t)h0 | ((uint32_t)h1 << 16),
                           (uint32_t)h2 | ((uint32_t)h3 << 16));
            *reinterpret_cast<uint2*>(sA2l + o) =
                make_uint2((uint32_t)l0 | ((uint32_t)l1 << 16),
                           (uint32_t)l2 | ((uint32_t)l3 << 16));
        }
    };

    auto loadA = [&](const float* __restrict__ src) {   // x chunk -> A region
        #pragma unroll
        for (int i = 0; i < 16; ++i) {
            int idx = tid + i * THREADS;
            int m   = idx >> 5;
            int k4  = (idx & 31) * 4;
            int gr  = r0 + m;
            float4 v = make_float4(0.f, 0.f, 0.f, 0.f);
            if (gr < N)
                v = __ldg(reinterpret_cast<const float4*>(src + (size_t)gr * D + k4));
            uint16_t h0,h1,h2,h3, l0,l1,l2,l3;
            split_bf16(v.x, h0, l0); split_bf16(v.y, h1, l1);
            split_bf16(v.z, h2, l2); split_bf16(v.w, h3, l3);
            int o = m * ASTRIDE + k4;
            *reinterpret_cast<uint2*>(sAh + o) =
                make_uint2((uint32_t)h0 | ((uint32_t)h1 << 16),
                           (uint32_t)h2 | ((uint32_t)h3 << 16));
            *reinterpret_cast<uint2*>(sAl + o) =
                make_uint2((uint32_t)l0 | ((uint32_t)l1 << 16),
                           (uint32_t)l2 | ((uint32_t)l3 << 16));
        }
    };
    auto loadB = [&](int chunk) {
        const uint4* gh = g_wt_hi + chunk * (128 * 128 / 8);
        const uint4* gl = g_wt_lo + chunk * (128 * 128 / 8);
        #pragma unroll
        for (int i = 0; i < 8; ++i) {
            int idx = tid + i * THREADS;
            int n   = idx >> 4;
            int k8  = (idx & 15) * 8;
            int o   = n * ASTRIDE + k8;
            *reinterpret_cast<uint4*>(sBh + o) = __ldg(gh + idx);
            *reinterpret_cast<uint4*>(sBl + o) = __ldg(gl + idx);
        }
    };
    auto initBias = [&](const float* __restrict__ b) {
        #pragma unroll
        for (int nt = 0; nt < 8; ++nt) {
            float2 bv = __ldg(reinterpret_cast<const float2*>(b + wn0 + nt * 8 + 2 * t4));
            #pragma unroll
            for (int mt = 0; mt < 2; ++mt) {
                c[mt][nt][0] = bv.x; c[mt][nt][1] = bv.y;
                c[mt][nt][2] = bv.x; c[mt][nt][3] = bv.y;
            }
        }
    };

    auto gemm = [&](uint32_t aOffH, uint32_t aOffL) {
        const uint32_t aBaseH = sbase + aOffH + aRowOff;
        const uint32_t aBaseL = sbase + aOffL + aRowOff;
        #pragma unroll 1
        for (int ks = 0; ks < 8; ++ks) {
            const uint32_t kb = ks * 32;
            uint32_t aH[2][4], aL[2][4], bH[8][2], bL[8][2];
            #pragma unroll
            for (int mt = 0; mt < 2; ++mt) {
                uint32_t off = (uint32_t)(mt * 16 * ROWB) + kb;
                ldsm_x4(aH[mt][0], aH[mt][1], aH[mt][2], aH[mt][3], aBaseH + off);
                ldsm_x4(aL[mt][0], aL[mt][1], aL[mt][2], aL[mt][3], aBaseL + off);
            }
            #pragma unroll
            for (int np = 0; np < 4; ++np) {
                uint32_t off = (uint32_t)(np * 16 * ROWB) + kb;
                ldsm_x4(bH[2*np][0], bH[2*np][1], bH[2*np+1][0], bH[2*np+1][1],
                        bBaseH + off);
                ldsm_x4(bL[2*np][0], bL[2*np][1], bL[2*np+1][0], bL[2*np+1][1],
                        bBaseL + off);
            }
            #pragma unroll
            for (int mt = 0; mt < 2; ++mt)
                #pragma unroll
                for (int nt = 0; nt < 8; ++nt) {
                    mma16816(c[mt][nt], aH[mt], bH[nt]);   // hi*hi
                    mma16816(c[mt][nt], aH[mt], bL[nt]);   // hi*lo
                    mma16816(c[mt][nt], aL[mt], bH[nt]);   // lo*hi
                }
        }
    };

    auto epi_to_A = [&]() {
        #pragma unroll
        for (int mt = 0; mt < 2; ++mt)
            #pragma unroll
            for (int nt = 0; nt < 8; ++nt) {
                int col = wn0 + nt * 8 + 2 * t4;
                #pragma unroll
                for (int half = 0; half < 2; ++half) {
                    int row = wr0 + mt * 16 + gid + half * 8;
                    float t0 = tanhf(c[mt][nt][half * 2 + 0]);
                    float t1 = tanhf(c[mt][nt][half * 2 + 1]);
                    uint16_t h0, l0, h1, l1;
                    split_bf16(t0, h0, l0); split_bf16(t1, h1, l1);
                    int o = row * ASTRIDE + col;
                    *reinterpret_cast<uint32_t*>(sAh + o) = (uint32_t)h0 | ((uint32_t)h1 << 16);
                    *reinterpret_cast<uint32_t*>(sAl + o) = (uint32_t)l0 | ((uint32_t)l1 << 16);
                }
            }
    };

    // ====================== Layer 1: [mi, mo, x] @ W1 ======================
    initBias(b1);
    loadB(0);
    gather();                                  // mi -> A, mo -> A2
    __syncthreads();
    gemm(OFF_A_HI, OFF_A_LO);                  // mi @ W1a
    __syncthreads();
    loadB(1);
    __syncthreads();
    gemm(OFF_A2_HI, OFF_A2_LO);                // mo @ W1b
    __syncthreads();
    loadA(x);                                  // x -> A
    loadB(2);
    __syncthreads();
    gemm(OFF_A_HI, OFF_A_LO);                  // x @ W1c
    __syncthreads();
    epi_to_A();

    // ====================== Layers 2..4 ====================================
    const float* bs[3] = { b2, b3, b4 };
    #pragma unroll 1
    for (int l = 0; l < 3; ++l) {
        __syncthreads();
        loadB(3 + l);
        __syncthreads();
        initBias(bs[l]);
        gemm(OFF_A_HI, OFF_A_LO);
        __syncthreads();
        if (l < 2) {
            epi_to_A();
        } else {
            float* sOut = reinterpret_cast<float*>(smem + OFF_B_HI);  // [128][132]
            #pragma unroll
            for (int mt = 0; mt < 2; ++mt)
                #pragma unroll
                for (int nt = 0; nt < 8; ++nt) {
                    int col = wn0 + nt * 8 + 2 * t4;
                    #pragma unroll
                    for (int half = 0; half < 2; ++half) {
                        int row = wr0 + mt * 16 + gid + half * 8;
                        float2 v;
                        v.x = tanhf(c[mt][nt][half * 2 + 0]);
                        v.y = tanhf(c[mt][nt][half * 2 + 1]);
                        *reinterpret_cast<float2*>(sOut + row * 132 + col) = v;
                    }
                }
            __syncthreads();
            #pragma unroll
            for (int i = 0; i < 16; ++i) {
                int idx = tid + i * THREADS;
                int m   = idx >> 5;
                int c4  = (idx & 31) * 4;
                int gr  = r0 + m;
                if (gr < N)
                    *reinterpret_cast<float4*>(out + (size_t)gr * D + c4) =
                        *reinterpret_cast<const float4*>(sOut + m * 132 + c4);
            }
        }
    }
}

// ---------------------------------------------------------------------------
// Host launcher (graph-capturable: kernel launches only)
// ---------------------------------------------------------------------------
extern "C" void kernel_launch(void* const* d_in, const int* in_sizes, int n_in,
                              void* d_out, int out_size) {
    const float* x    = (const float*)d_in[0];
    const float* ew   = (const float*)d_in[1];
    const void*  eidx = d_in[2];
    const float* W1   = (const float*)d_in[3];
    const float* b1   = (const float*)d_in[4];
    const float* W2   = (const float*)d_in[5];
    const float* b2   = (const float*)d_in[6];
    const float* W3   = (const float*)d_in[7];
    const float* b3   = (const float*)d_in[8];
    const float* W4   = (const float*)d_in[9];
    const float* b4   = (const float*)d_in[10];
    float*       out  = (float*)d_out;

    const int N = in_sizes[0] / D;        // 50000
    const int E = in_sizes[2] / 2;        // 800000

    detect_idx_kernel<<<1, 32>>>(eidx, E, N);

    // ---- incidence CSR build ----
    zero_deg_kernel<<<(N + 255) / 256, 256>>>(N);
    hist_kernel<<<(E + 255) / 256, 256>>>(eidx, E, N);
    {
        int nblk = (N + SCAN_B - 1) / SCAN_B;          // 49
        scan_block_kernel<<<nblk, SCAN_B>>>(N);
        scan_tops_kernel<<<1, 64>>>(nblk);
        scan_add_kernel<<<nblk, SCAN_B>>>(N);
    }
    fill_kernel<<<(E + 255) / 256, 256>>>(eidx, ew, E, N);

    // ---- weight prep ----
    {
        int total = 6 * 128 * 128;
        prep_w_kernel<<<(total + 255) / 256, 256>>>(W1, W2, W3, W4);
    }

    // ---- fused aggregation + MLP ----
    {
        cudaFuncSetAttribute(fused_kernel,
                             cudaFuncAttributeMaxDynamicSharedMemorySize, SMEM_TOTAL);
        int blocks = (N + TILE_M - 1) / TILE_M;     // 391
        fused_kernel<<<blocks, THREADS, SMEM_TOTAL>>>(x, b1, b2, b3, b4, out, N);
    }
}

// round 16
// speedup vs baseline: 2.2300x; 2.2300x over previous
#include <cuda_runtime.h>
#include <cuda_bf16.h>
#include <cstdint>

#define D        128
#define MAX_N    50000
#define MAX_E    800000
#define MTILE    64           // MLP node rows per block
#define THREADS  256
#define ASTRIDE  136          // padded bf16 stride: rows 4 banks apart
#define SCAN_B   1024         // scan block size

// Scratch (static __device__ globals: allowed)
__device__ float g_mi[MAX_N * D];
__device__ float g_mo[MAX_N * D];
__device__ int   g_idx_is64;

// Incidence-CSR scratch
__device__ int  g_off[MAX_N + 1];
__device__ int  g_cur[MAX_N];
__device__ int  g_tmp[MAX_N];
__device__ int  g_bsum[64];
__device__ int2 g_ent[2 * MAX_E];     // (other_node, weight_bits | flag<<31)

// Pre-split, pre-transposed weights: 6 chunks of [n=128][k=128] bf16.
__device__ uint4 g_wt_hi[6 * 128 * 128 / 8];
__device__ uint4 g_wt_lo[6 * 128 * 128 / 8];

// ---------------------------------------------------------------------------
__device__ __forceinline__ void split_bf16(float f, uint16_t& h, uint16_t& l) {
    __nv_bfloat16 hi = __float2bfloat16_rn(f);
    __nv_bfloat16 lo = __float2bfloat16_rn(f - __bfloat162float(hi));
    h = __bfloat16_as_ushort(hi);
    l = __bfloat16_as_ushort(lo);
}

__device__ __forceinline__ void mma16816(float c[4], const uint32_t a[4],
                                         const uint32_t b[2]) {
    asm volatile(
        "mma.sync.aligned.m16n8k16.row.col.f32.bf16.bf16.f32 "
        "{%0,%1,%2,%3}, {%4,%5,%6,%7}, {%8,%9}, {%0,%1,%2,%3};"
        : "+f"(c[0]), "+f"(c[1]), "+f"(c[2]), "+f"(c[3])
        : "r"(a[0]), "r"(a[1]), "r"(a[2]), "r"(a[3]), "r"(b[0]), "r"(b[1]));
}

__device__ __forceinline__ void ldsm_x4(uint32_t& r0, uint32_t& r1,
                                        uint32_t& r2, uint32_t& r3,
                                        uint32_t addr) {
    asm volatile("ldmatrix.sync.aligned.m8n8.x4.shared.b16 {%0,%1,%2,%3}, [%4];"
                 : "=r"(r0), "=r"(r1), "=r"(r2), "=r"(r3) : "r"(addr));
}

__device__ __forceinline__ uint32_t smem_u32(const void* p) {
    uint32_t a;
    asm("{ .reg .u64 t; cvta.to.shared.u64 t, %1; cvt.u32.u64 %0, t; }"
        : "=r"(a) : "l"(p));
    return a;
}

__device__ __forceinline__ void load_edge(const void* eidx, int E, int N,
                                          int e, int& src, int& dst) {
    if (g_idx_is64) {
        const long long* p = (const long long*)eidx;
        src = (int)p[e];
        dst = (int)p[(size_t)E + e];
    } else {
        const int* p = (const int*)eidx;
        src = p[e];
        dst = p[(size_t)E + e];
    }
    src = min(max(src, 0), N - 1);
    dst = min(max(dst, 0), N - 1);
}

// ===========================================================================
// Kernel 0: detect edge_index dtype
// ===========================================================================
__global__ void detect_idx_kernel(const void* __restrict__ eidx, int E, int N) {
    if (threadIdx.x != 0 || blockIdx.x != 0) return;
    const long long* p64 = (const long long*)eidx;
    int stride = E / 64; if (stride < 1) stride = 1;
    int ok = 1;
    for (int i = 0; i < 64; ++i) {
        long long v = p64[(long long)i * stride];
        if (v < 0 || v >= N) { ok = 0; break; }
    }
    g_idx_is64 = ok;
}

// ===========================================================================
// CSR build: zero-deg -> histogram -> 3-phase scan -> fill
// ===========================================================================
__global__ void zero_deg_kernel(int N) {
    int i = blockIdx.x * blockDim.x + threadIdx.x;
    if (i < N) g_off[i] = 0;
}

__global__ void hist_kernel(const void* __restrict__ eidx, int E, int N) {
    int e = blockIdx.x * blockDim.x + threadIdx.x;
    if (e >= E) return;
    int src, dst;
    load_edge(eidx, E, N, e, src, dst);
    atomicAdd(&g_off[dst], 1);
    atomicAdd(&g_off[src], 1);
}

__global__ void scan_block_kernel(int N) {
    __shared__ int wsum[32];
    int i    = blockIdx.x * SCAN_B + threadIdx.x;
    int lane = threadIdx.x & 31;
    int w    = threadIdx.x >> 5;

    int v = (i < N) ? g_off[i] : 0;
    int incl = v;
    #pragma unroll
    for (int d = 1; d < 32; d <<= 1) {
        int t = __shfl_up_sync(0xffffffff, incl, d);
        if (lane >= d) incl += t;
    }
    if (lane == 31) wsum[w] = incl;
    __syncthreads();
    if (w == 0) {
        int s = wsum[lane];
        #pragma unroll
        for (int d = 1; d < 32; d <<= 1) {
            int t = __shfl_up_sync(0xffffffff, s, d);
            if (lane >= d) s += t;
        }
        wsum[lane] = s;
    }
    __syncthreads();
    int wo = (w > 0) ? wsum[w - 1] : 0;
    if (i < N) g_tmp[i] = incl - v + wo;
    if (threadIdx.x == SCAN_B - 1) g_bsum[blockIdx.x] = wsum[31];
}

__global__ void scan_tops_kernel(int nblk) {
    __shared__ int s[64];
    int t = threadIdx.x;
    s[t] = (t < nblk) ? g_bsum[t] : 0;
    __syncthreads();
    #pragma unroll
    for (int d = 1; d < 64; d <<= 1) {
        int v = (t >= d) ? s[t - d] : 0;
        __syncthreads();
        s[t] += v;
        __syncthreads();
    }
    g_bsum[t] = s[t];
}

__global__ void scan_add_kernel(int N) {
    int i = blockIdx.x * SCAN_B + threadIdx.x;
    if (i < N) {
        int base = (blockIdx.x > 0) ? g_bsum[blockIdx.x - 1] : 0;
        int v = g_tmp[i] + base;
        g_off[i] = v;
        g_cur[i] = v;
    }
    if (i == 0) g_off[N] = g_bsum[(N + SCAN_B - 1) / SCAN_B - 1];
}

__global__ void fill_kernel(const void* __restrict__ eidx,
                            const float* __restrict__ ew, int E, int N) {
    int e = blockIdx.x * blockDim.x + threadIdx.x;
    if (e >= E) return;
    int src, dst;
    load_edge(eidx, E, N, e, src, dst);
    int wbits = __float_as_int(__ldg(&ew[e]));
    int p1 = atomicAdd(&g_cur[dst], 1);
    g_ent[p1] = make_int2(src, wbits);                    // mi[dst] += w*x[src]
    int p2 = atomicAdd(&g_cur[src], 1);
    g_ent[p2] = make_int2(dst, wbits | (int)0x80000000);  // mo[src] += w*x[dst]
}

// ===========================================================================
// Aggregate: one warp per node, atomic-free single-write outputs.
// ===========================================================================
__global__ void __launch_bounds__(256)
aggregate_kernel(const float* __restrict__ x, int N) {
    int wid  = threadIdx.x >> 5;
    int lane = threadIdx.x & 31;
    int n    = blockIdx.x * 8 + wid;
    if (n >= N) return;

    int s = g_off[n];
    int t = g_off[n + 1];

    float4 mi = make_float4(0.f, 0.f, 0.f, 0.f);
    float4 mo = make_float4(0.f, 0.f, 0.f, 0.f);

    for (int j = s; j < t; ++j) {
        int2 ent = __ldg(&g_ent[j]);                       // warp-uniform
        float e  = __int_as_float(ent.y & 0x7fffffff);
        float4 v = __ldg(reinterpret_cast<const float4*>(
                             x + (size_t)ent.x * D) + lane);
        if (ent.y < 0) {
            mo.x = fmaf(e, v.x, mo.x); mo.y = fmaf(e, v.y, mo.y);
            mo.z = fmaf(e, v.z, mo.z); mo.w = fmaf(e, v.w, mo.w);
        } else {
            mi.x = fmaf(e, v.x, mi.x); mi.y = fmaf(e, v.y, mi.y);
            mi.z = fmaf(e, v.z, mi.z); mi.w = fmaf(e, v.w, mi.w);
        }
    }
    reinterpret_cast<float4*>(g_mi + (size_t)n * D)[lane] = mi;
    reinterpret_cast<float4*>(g_mo + (size_t)n * D)[lane] = mo;
}

// ===========================================================================
// Kernel P: pre-split + transpose weights into g_wt_hi/lo [chunk][n][k]
// ===========================================================================
__global__ void prep_w_kernel(const float* __restrict__ W1,
                              const float* __restrict__ W2,
                              const float* __restrict__ W3,
                              const float* __restrict__ W4) {
    int id = blockIdx.x * blockDim.x + threadIdx.x;
    if (id >= 6 * 128 * 128) return;
    int c = id >> 14;
    int n = (id >> 7) & 127;
    int k = id & 127;
    const float* src = (c < 3) ? (W1 + (size_t)c * 128 * 128)
                     : (c == 3) ? W2 : (c == 4) ? W3 : W4;
    float w = src[(size_t)k * 128 + n];               // W[k][n] -> B[n][k]
    uint16_t h, l;
    split_bf16(w, h, l);
    reinterpret_cast<uint16_t*>(g_wt_hi)[id] = h;
    reinterpret_cast<uint16_t*>(g_wt_lo)[id] = l;
}

// ===========================================================================
// Kernel 3: fused 4-layer MLP, mma.sync bf16-split, ldmatrix, MTILE=64.
//   smem: A_HI/A_LO 64 rows (17408 B each), B_HI/B_LO 128 rows (34816 B each)
//   = 104448 B -> 2 CTAs/SM (16 warps).
//   Warp w: rows 16*(w&3).., cols 64*(w>>2)..; one m16n8k16 A fragment per ks.
// ===========================================================================
#define RB_A      (MTILE * ASTRIDE * 2)              // 17408
#define RB_B      (128 * ASTRIDE * 2)                // 34816
#define OFF_A_HI  0
#define OFF_A_LO  (OFF_A_HI + RB_A)
#define OFF_B_HI  (OFF_A_LO + RB_A)
#define OFF_B_LO  (OFF_B_HI + RB_B)
#define SMEM_TOTAL (OFF_B_LO + RB_B)                 // 104448 B
#define ROWB      (ASTRIDE * 2)                      // 272 bytes per tile row

__global__ void __launch_bounds__(THREADS, 2)
mlp_mma_kernel(const float* __restrict__ x,
               const float* __restrict__ b1, const float* __restrict__ b2,
               const float* __restrict__ b3, const float* __restrict__ b4,
               float* __restrict__ out, int N) {
    extern __shared__ char smem[];
    uint16_t* sAh = reinterpret_cast<uint16_t*>(smem + OFF_A_HI);
    uint16_t* sAl = reinterpret_cast<uint16_t*>(smem + OFF_A_LO);
    uint16_t* sBh = reinterpret_cast<uint16_t*>(smem + OFF_B_HI);
    uint16_t* sBl = reinterpret_cast<uint16_t*>(smem + OFF_B_LO);
    const uint32_t sbase = smem_u32(smem);

    const int tid  = threadIdx.x;
    const int wid  = tid >> 5;
    const int lane = tid & 31;
    const int gid  = lane >> 2;
    const int t4   = lane & 3;
    const int wr0  = (wid & 3) * 16;     // 16 rows per warp
    const int wn0  = (wid >> 2) * 64;    // 64 cols per warp
    const int r0   = blockIdx.x * MTILE;

    // ldmatrix per-lane source rows:
    //   A (x4: m0-7/k0, m8-15/k0, m0-7/k8, m8-15/k8) = full m16n8k16 A frag
    const int a_row = wr0 + (lane & 7) + ((lane >> 3) & 1) * 8;
    const int a_kof = ((lane >> 4) & 1) * 8;
    //   B (x4: n0-7/k0, n0-7/k8, n8-15/k0, n8-15/k8)
    const int b_row = wn0 + (lane & 7) + ((lane >> 4) & 1) * 8;
    const int b_kof = ((lane >> 3) & 1) * 8;

    const uint32_t aBaseH = sbase + OFF_A_HI + (uint32_t)(a_row * ROWB + a_kof * 2);
    const uint32_t aBaseL = sbase + OFF_A_LO + (uint32_t)(a_row * ROWB + a_kof * 2);
    const uint32_t bBaseH = sbase + OFF_B_HI + (uint32_t)(b_row * ROWB + b_kof * 2);
    const uint32_t bBaseL = sbase + OFF_B_LO + (uint32_t)(b_row * ROWB + b_kof * 2);

    float c[8][4];                       // [n-tile][frag] for 16 rows

    auto loadA = [&](const float* __restrict__ src) {
        #pragma unroll
        for (int i = 0; i < (MTILE * D / 4) / THREADS; ++i) {   // 8
            int idx = tid + i * THREADS;
            int m   = idx >> 5;
            int k4  = (idx & 31) * 4;
            int gr  = r0 + m;
            float4 v = make_float4(0.f, 0.f, 0.f, 0.f);
            if (gr < N)
                v = __ldg(reinterpret_cast<const float4*>(src + (size_t)gr * D + k4));
            uint16_t h0,h1,h2,h3, l0,l1,l2,l3;
            split_bf16(v.x, h0, l0); split_bf16(v.y, h1, l1);
            split_bf16(v.z, h2, l2); split_bf16(v.w, h3, l3);
            int o = m * ASTRIDE + k4;
            *reinterpret_cast<uint2*>(sAh + o) =
                make_uint2((uint32_t)h0 | ((uint32_t)h1 << 16),
                           (uint32_t)h2 | ((uint32_t)h3 << 16));
            *reinterpret_cast<uint2*>(sAl + o) =
                make_uint2((uint32_t)l0 | ((uint32_t)l1 << 16),
                           (uint32_t)l2 | ((uint32_t)l3 << 16));
        }
    };
    auto loadB = [&](int chunk) {
        const uint4* gh = g_wt_hi + chunk * (128 * 128 / 8);
        const uint4* gl = g_wt_lo + chunk * (128 * 128 / 8);
        #pragma unroll
        for (int i = 0; i < 8; ++i) {
            int idx = tid + i * THREADS;
            int n   = idx >> 4;
            int k8  = (idx & 15) * 8;
            int o   = n * ASTRIDE + k8;
            *reinterpret_cast<uint4*>(sBh + o) = __ldg(gh + idx);
            *reinterpret_cast<uint4*>(sBl + o) = __ldg(gl + idx);
        }
    };
    auto initBias = [&](const float* __restrict__ b) {
        #pragma unroll
        for (int nt = 0; nt < 8; ++nt) {
            float2 bv = __ldg(reinterpret_cast<const float2*>(b + wn0 + nt * 8 + 2 * t4));
            c[nt][0] = bv.x; c[nt][1] = bv.y;
            c[nt][2] = bv.x; c[nt][3] = bv.y;
        }
    };

    auto gemm = [&]() {
        #pragma unroll 1
        for (int ks = 0; ks < 8; ++ks) {
            const uint32_t kb = ks * 32;            // 16 bf16 = 32 bytes
            uint32_t aH[4], aL[4], bH[8][2], bL[8][2];
            ldsm_x4(aH[0], aH[1], aH[2], aH[3], aBaseH + kb);
            ldsm_x4(aL[0], aL[1], aL[2], aL[3], aBaseL + kb);
            #pragma unroll
            for (int np = 0; np < 4; ++np) {
                uint32_t off = (uint32_t)(np * 16 * ROWB) + kb;
                ldsm_x4(bH[2*np][0], bH[2*np][1], bH[2*np+1][0], bH[2*np+1][1],
                        bBaseH + off);
                ldsm_x4(bL[2*np][0], bL[2*np][1], bL[2*np+1][0], bL[2*np+1][1],
                        bBaseL + off);
            }
            #pragma unroll
            for (int nt = 0; nt < 8; ++nt) {
                mma16816(c[nt], aH, bH[nt]);   // hi*hi
                mma16816(c[nt], aH, bL[nt]);   // hi*lo
                mma16816(c[nt], aL, bH[nt]);   // lo*hi
            }
        }
    };

    auto epi_to_A = [&]() {
        #pragma unroll
        for (int nt = 0; nt < 8; ++nt) {
            int col = wn0 + nt * 8 + 2 * t4;
            #pragma unroll
            for (int half = 0; half < 2; ++half) {
                int row = wr0 + gid + half * 8;
                float t0 = tanhf(c[nt][half * 2 + 0]);
                float t1 = tanhf(c[nt][half * 2 + 1]);
                uint16_t h0, l0, h1, l1;
                split_bf16(t0, h0, l0); split_bf16(t1, h1, l1);
                int o = row * ASTRIDE + col;
                *reinterpret_cast<uint32_t*>(sAh + o) = (uint32_t)h0 | ((uint32_t)h1 << 16);
                *reinterpret_cast<uint32_t*>(sAl + o) = (uint32_t)l0 | ((uint32_t)l1 << 16);
            }
        }
    };

    // ====================== Layer 1: [mi, mo, x] @ W1 ======================
    initBias(b1);
    #pragma unroll 1
    for (int p = 0; p < 3; ++p) {
        __syncthreads();
        loadA(p == 0 ? (const float*)g_mi : p == 1 ? (const float*)g_mo : x);
        loadB(p);
        __syncthreads();
        gemm();
    }
    __syncthreads();
    epi_to_A();

    // ====================== Layers 2..4 ====================================
    const float* bs[3] = { b2, b3, b4 };
    #pragma unroll 1
    for (int l = 0; l < 3; ++l) {
        __syncthreads();
        loadB(3 + l);
        __syncthreads();
        initBias(bs[l]);
        gemm();
        __syncthreads();
        if (l < 2) {
            epi_to_A();
        } else {
            float* sOut = reinterpret_cast<float*>(smem + OFF_B_HI);  // [64][132]
            #pragma unroll
            for (int nt = 0; nt < 8; ++nt) {
                int col = wn0 + nt * 8 + 2 * t4;
                #pragma unroll
                for (int half = 0; half < 2; ++half) {
                    int row = wr0 + gid + half * 8;
                    float2 v;
                    v.x = tanhf(c[nt][half * 2 + 0]);
                    v.y = tanhf(c[nt][half * 2 + 1]);
                    *reinterpret_cast<float2*>(sOut + row * 132 + col) = v;
                }
            }
            __syncthreads();
            #pragma unroll
            for (int i = 0; i < (MTILE * D / 4) / THREADS; ++i) {   // 8
                int idx = tid + i * THREADS;
                int m   = idx >> 5;
                int c4  = (idx & 31) * 4;
                int gr  = r0 + m;
                if (gr < N)
                    *reinterpret_cast<float4*>(out + (size_t)gr * D + c4) =
                        *reinterpret_cast<const float4*>(sOut + m * 132 + c4);
            }
        }
    }
}

// ---------------------------------------------------------------------------
// Host launcher (graph-capturable: kernel launches only)
// ---------------------------------------------------------------------------
extern "C" void kernel_launch(void* const* d_in, const int* in_sizes, int n_in,
                              void* d_out, int out_size) {
    const float* x    = (const float*)d_in[0];
    const float* ew   = (const float*)d_in[1];
    const void*  eidx = d_in[2];
    const float* W1   = (const float*)d_in[3];
    const float* b1   = (const float*)d_in[4];
    const float* W2   = (const float*)d_in[5];
    const float* b2   = (const float*)d_in[6];
    const float* W3   = (const float*)d_in[7];
    const float* b3   = (const float*)d_in[8];
    const float* W4   = (const float*)d_in[9];
    const float* b4   = (const float*)d_in[10];
    float*       out  = (float*)d_out;

    const int N = in_sizes[0] / D;        // 50000
    const int E = in_sizes[2] / 2;        // 800000

    detect_idx_kernel<<<1, 32>>>(eidx, E, N);

    // ---- incidence CSR build ----
    zero_deg_kernel<<<(N + 255) / 256, 256>>>(N);
    hist_kernel<<<(E + 255) / 256, 256>>>(eidx, E, N);
    {
        int nblk = (N + SCAN_B - 1) / SCAN_B;          // 49
        scan_block_kernel<<<nblk, SCAN_B>>>(N);
        scan_tops_kernel<<<1, 64>>>(nblk);
        scan_add_kernel<<<nblk, SCAN_B>>>(N);
    }
    fill_kernel<<<(E + 255) / 256, 256>>>(eidx, ew, E, N);

    // ---- weight prep ----
    {
        int total = 6 * 128 * 128;
        prep_w_kernel<<<(total + 255) / 256, 256>>>(W1, W2, W3, W4);
    }

    // ---- atomic-free aggregation: warp per node ----
    aggregate_kernel<<<(N + 7) / 8, 256>>>(x, N);

    // ---- fused MLP (mma.sync bf16-split + ldmatrix, MTILE=64) ----
    {
        cudaFuncSetAttribute(mlp_mma_kernel,
                             cudaFuncAttributeMaxDynamicSharedMemorySize, SMEM_TOTAL);
        int blocks = (N + MTILE - 1) / MTILE;       // 782
        mlp_mma_kernel<<<blocks, THREADS, SMEM_TOTAL>>>(x, b1, b2, b3, b4, out, N);
    }
}

// round 17
// speedup vs baseline: 2.2513x; 1.0096x over previous
#include <cuda_runtime.h>
#include <cuda_bf16.h>
#include <cstdint>

#define D        128
#define MAX_N    50000
#define MAX_E    800000
#define MTILE    64           // MLP node rows per block
#define THREADS  256
#define ASTRIDE  136          // padded bf16 stride: rows 4 banks apart
#define SCAN_B   1024         // scan block size

__device__ int   g_idx_is64;

// Aggregated messages, pre-split bf16 (hi/lo), row-major [node][128]
__device__ uint16_t g_mih[MAX_N * D];
__device__ uint16_t g_mil[MAX_N * D];
__device__ uint16_t g_moh[MAX_N * D];
__device__ uint16_t g_mol[MAX_N * D];

// Incidence-CSR scratch
__device__ int  g_off[MAX_N + 1];
__device__ int  g_cur[MAX_N];
__device__ int  g_tmp[MAX_N];
__device__ int  g_bsum[64];
__device__ int2 g_ent[2 * MAX_E];     // (other_node, weight_bits | flag<<31)

// Pre-split, pre-transposed weights: 6 chunks of [n=128][k=128] bf16.
__device__ uint4 g_wt_hi[6 * 128 * 128 / 8];
__device__ uint4 g_wt_lo[6 * 128 * 128 / 8];

// ---------------------------------------------------------------------------
__device__ __forceinline__ void split_bf16(float f, uint16_t& h, uint16_t& l) {
    __nv_bfloat16 hi = __float2bfloat16_rn(f);
    __nv_bfloat16 lo = __float2bfloat16_rn(f - __bfloat162float(hi));
    h = __bfloat16_as_ushort(hi);
    l = __bfloat16_as_ushort(lo);
}

__device__ __forceinline__ void mma16816(float c[4], const uint32_t a[4],
                                         const uint32_t b[2]) {
    asm volatile(
        "mma.sync.aligned.m16n8k16.row.col.f32.bf16.bf16.f32 "
        "{%0,%1,%2,%3}, {%4,%5,%6,%7}, {%8,%9}, {%0,%1,%2,%3};"
        : "+f"(c[0]), "+f"(c[1]), "+f"(c[2]), "+f"(c[3])
        : "r"(a[0]), "r"(a[1]), "r"(a[2]), "r"(a[3]), "r"(b[0]), "r"(b[1]));
}

__device__ __forceinline__ void ldsm_x4(uint32_t& r0, uint32_t& r1,
                                        uint32_t& r2, uint32_t& r3,
                                        uint32_t addr) {
    asm volatile("ldmatrix.sync.aligned.m8n8.x4.shared.b16 {%0,%1,%2,%3}, [%4];"
                 : "=r"(r0), "=r"(r1), "=r"(r2), "=r"(r3) : "r"(addr));
}

__device__ __forceinline__ uint32_t smem_u32(const void* p) {
    uint32_t a;
    asm("{ .reg .u64 t; cvta.to.shared.u64 t, %1; cvt.u32.u64 %0, t; }"
        : "=r"(a) : "l"(p));
    return a;
}

__device__ __forceinline__ void load_edge(const void* eidx, int E, int N,
                                          int e, int& src, int& dst) {
    if (g_idx_is64) {
        const long long* p = (const long long*)eidx;
        src = (int)p[e];
        dst = (int)p[(size_t)E + e];
    } else {
        const int* p = (const int*)eidx;
        src = p[e];
        dst = p[(size_t)E + e];
    }
    src = min(max(src, 0), N - 1);
    dst = min(max(dst, 0), N - 1);
}

// ===========================================================================
// Kernel 1: zero degree counters + (block 0) detect edge_index dtype
// ===========================================================================
__global__ void zero_deg_kernel(const void* __restrict__ eidx, int E, int N) {
    int i = blockIdx.x * blockDim.x + threadIdx.x;
    if (i < N) g_off[i] = 0;
    if (blockIdx.x == 0 && threadIdx.x == 0) {
        const long long* p64 = (const long long*)eidx;
        int stride = E / 64; if (stride < 1) stride = 1;
        int ok = 1;
        for (int s = 0; s < 64; ++s) {
            long long v = p64[(long long)s * stride];
            if (v < 0 || v >= N) { ok = 0; break; }
        }
        g_idx_is64 = ok;
    }
}

__global__ void hist_kernel(const void* __restrict__ eidx, int E, int N) {
    int e = blockIdx.x * blockDim.x + threadIdx.x;
    if (e >= E) return;
    int src, dst;
    load_edge(eidx, E, N, e, src, dst);
    atomicAdd(&g_off[dst], 1);
    atomicAdd(&g_off[src], 1);
}

__global__ void scan_block_kernel(int N) {
    __shared__ int wsum[32];
    int i    = blockIdx.x * SCAN_B + threadIdx.x;
    int lane = threadIdx.x & 31;
    int w    = threadIdx.x >> 5;

    int v = (i < N) ? g_off[i] : 0;
    int incl = v;
    #pragma unroll
    for (int d = 1; d < 32; d <<= 1) {
        int t = __shfl_up_sync(0xffffffff, incl, d);
        if (lane >= d) incl += t;
    }
    if (lane == 31) wsum[w] = incl;
    __syncthreads();
    if (w == 0) {
        int s = wsum[lane];
        #pragma unroll
        for (int d = 1; d < 32; d <<= 1) {
            int t = __shfl_up_sync(0xffffffff, s, d);
            if (lane >= d) s += t;
        }
        wsum[lane] = s;
    }
    __syncthreads();
    int wo = (w > 0) ? wsum[w - 1] : 0;
    if (i < N) g_tmp[i] = incl - v + wo;
    if (threadIdx.x == SCAN_B - 1) g_bsum[blockIdx.x] = wsum[31];
}

__global__ void scan_tops_kernel(int nblk) {
    __shared__ int s[64];
    int t = threadIdx.x;
    s[t] = (t < nblk) ? g_bsum[t] : 0;
    __syncthreads();
    #pragma unroll
    for (int d = 1; d < 64; d <<= 1) {
        int v = (t >= d) ? s[t - d] : 0;
        __syncthreads();
        s[t] += v;
        __syncthreads();
    }
    g_bsum[t] = s[t];
}

__global__ void scan_add_kernel(int N) {
    int i = blockIdx.x * SCAN_B + threadIdx.x;
    if (i < N) {
        int base = (blockIdx.x > 0) ? g_bsum[blockIdx.x - 1] : 0;
        int v = g_tmp[i] + base;
        g_off[i] = v;
        g_cur[i] = v;
    }
    if (i == 0) g_off[N] = g_bsum[(N + SCAN_B - 1) / SCAN_B - 1];
}

__global__ void fill_kernel(const void* __restrict__ eidx,
                            const float* __restrict__ ew, int E, int N) {
    int e = blockIdx.x * blockDim.x + threadIdx.x;
    if (e >= E) return;
    int src, dst;
    load_edge(eidx, E, N, e, src, dst);
    int wbits = __float_as_int(__ldg(&ew[e]));
    int p1 = atomicAdd(&g_cur[dst], 1);
    g_ent[p1] = make_int2(src, wbits);                    // mi[dst] += w*x[src]
    int p2 = atomicAdd(&g_cur[src], 1);
    g_ent[p2] = make_int2(dst, wbits | (int)0x80000000);  // mo[src] += w*x[dst]
}

// ===========================================================================
// Aggregate: one warp per node; outputs pre-split bf16 hi/lo (ALU work
// hidden under the LTS-bound gather).
// ===========================================================================
__global__ void __launch_bounds__(256)
aggregate_kernel(const float* __restrict__ x, int N) {
    int wid  = threadIdx.x >> 5;
    int lane = threadIdx.x & 31;
    int n    = blockIdx.x * 8 + wid;
    if (n >= N) return;

    int s = g_off[n];
    int t = g_off[n + 1];

    float4 mi = make_float4(0.f, 0.f, 0.f, 0.f);
    float4 mo = make_float4(0.f, 0.f, 0.f, 0.f);

    for (int j = s; j < t; ++j) {
        int2 ent = __ldg(&g_ent[j]);                       // warp-uniform
        float e  = __int_as_float(ent.y & 0x7fffffff);
        float4 v = __ldg(reinterpret_cast<const float4*>(
                             x + (size_t)ent.x * D) + lane);
        if (ent.y < 0) {
            mo.x = fmaf(e, v.x, mo.x); mo.y = fmaf(e, v.y, mo.y);
            mo.z = fmaf(e, v.z, mo.z); mo.w = fmaf(e, v.w, mo.w);
        } else {
            mi.x = fmaf(e, v.x, mi.x); mi.y = fmaf(e, v.y, mi.y);
            mi.z = fmaf(e, v.z, mi.z); mi.w = fmaf(e, v.w, mi.w);
        }
    }

    size_t o = (size_t)n * D + lane * 4;     // 8B-aligned (lane*4*2B)
    uint16_t h0,h1,h2,h3, l0,l1,l2,l3;
    split_bf16(mi.x, h0, l0); split_bf16(mi.y, h1, l1);
    split_bf16(mi.z, h2, l2); split_bf16(mi.w, h3, l3);
    *reinterpret_cast<uint2*>(g_mih + o) =
        make_uint2((uint32_t)h0 | ((uint32_t)h1 << 16),
                   (uint32_t)h2 | ((uint32_t)h3 << 16));
    *reinterpret_cast<uint2*>(g_mil + o) =
        make_uint2((uint32_t)l0 | ((uint32_t)l1 << 16),
                   (uint32_t)l2 | ((uint32_t)l3 << 16));
    split_bf16(mo.x, h0, l0); split_bf16(mo.y, h1, l1);
    split_bf16(mo.z, h2, l2); split_bf16(mo.w, h3, l3);
    *reinterpret_cast<uint2*>(g_moh + o) =
        make_uint2((uint32_t)h0 | ((uint32_t)h1 << 16),
                   (uint32_t)h2 | ((uint32_t)h3 << 16));
    *reinterpret_cast<uint2*>(g_mol + o) =
        make_uint2((uint32_t)l0 | ((uint32_t)l1 << 16),
                   (uint32_t)l2 | ((uint32_t)l3 << 16));
}

// ===========================================================================
// Kernel P: pre-split + transpose weights into g_wt_hi/lo [chunk][n][k]
// ===========================================================================
__global__ void prep_w_kernel(const float* __restrict__ W1,
                              const float* __restrict__ W2,
                              const float* __restrict__ W3,
                              const float* __restrict__ W4) {
    int id = blockIdx.x * blockDim.x + threadIdx.x;
    if (id >= 6 * 128 * 128) return;
    int c = id >> 14;
    int n = (id >> 7) & 127;
    int k = id & 127;
    const float* src = (c < 3) ? (W1 + (size_t)c * 128 * 128)
                     : (c == 3) ? W2 : (c == 4) ? W3 : W4;
    float w = src[(size_t)k * 128 + n];               // W[k][n] -> B[n][k]
    uint16_t h, l;
    split_bf16(w, h, l);
    reinterpret_cast<uint16_t*>(g_wt_hi)[id] = h;
    reinterpret_cast<uint16_t*>(g_wt_lo)[id] = l;
}

// ===========================================================================
// Kernel 3: fused 4-layer MLP, mma.sync bf16-split, ldmatrix, MTILE=64.
//   mi/mo arrive pre-split -> pure uint4 copies; only x is converted here.
// ===========================================================================
#define RB_A      (MTILE * ASTRIDE * 2)              // 17408
#define RB_B      (128 * ASTRIDE * 2)                // 34816
#define OFF_A_HI  0
#define OFF_A_LO  (OFF_A_HI + RB_A)
#define OFF_B_HI  (OFF_A_LO + RB_A)
#define OFF_B_LO  (OFF_B_HI + RB_B)
#define SMEM_TOTAL (OFF_B_LO + RB_B)                 // 104448 B
#define ROWB      (ASTRIDE * 2)                      // 272 bytes per tile row

__global__ void __launch_bounds__(THREADS, 2)
mlp_mma_kernel(const float* __restrict__ x,
               const float* __restrict__ b1, const float* __restrict__ b2,
               const float* __restrict__ b3, const float* __restrict__ b4,
               float* __restrict__ out, int N) {
    extern __shared__ char smem[];
    uint16_t* sAh = reinterpret_cast<uint16_t*>(smem + OFF_A_HI);
    uint16_t* sAl = reinterpret_cast<uint16_t*>(smem + OFF_A_LO);
    uint16_t* sBh = reinterpret_cast<uint16_t*>(smem + OFF_B_HI);
    uint16_t* sBl = reinterpret_cast<uint16_t*>(smem + OFF_B_LO);
    const uint32_t sbase = smem_u32(smem);

    const int tid  = threadIdx.x;
    const int wid  = tid >> 5;
    const int lane = tid & 31;
    const int gid  = lane >> 2;
    const int t4   = lane & 3;
    const int wr0  = (wid & 3) * 16;     // 16 rows per warp
    const int wn0  = (wid >> 2) * 64;    // 64 cols per warp
    const int r0   = blockIdx.x * MTILE;

    const int a_row = wr0 + (lane & 7) + ((lane >> 3) & 1) * 8;
    const int a_kof = ((lane >> 4) & 1) * 8;
    const int b_row = wn0 + (lane & 7) + ((lane >> 4) & 1) * 8;
    const int b_kof = ((lane >> 3) & 1) * 8;

    const uint32_t aBaseH = sbase + OFF_A_HI + (uint32_t)(a_row * ROWB + a_kof * 2);
    const uint32_t aBaseL = sbase + OFF_A_LO + (uint32_t)(a_row * ROWB + a_kof * 2);
    const uint32_t bBaseH = sbase + OFF_B_HI + (uint32_t)(b_row * ROWB + b_kof * 2);
    const uint32_t bBaseL = sbase + OFF_B_LO + (uint32_t)(b_row * ROWB + b_kof * 2);

    float c[8][4];

    // mi/mo: straight copy of pre-split rows (no conversion)
    auto copyA = [&](const uint16_t* __restrict__ gh,
                     const uint16_t* __restrict__ gl) {
        #pragma unroll
        for (int i = 0; i < (MTILE * D * 2 / 16) / THREADS; ++i) {   // 4
            int idx = tid + i * THREADS;         // uint4 = 8 bf16
            int m   = idx >> 4;                  // 16 uint4 per 128-col row
            int k8  = (idx & 15) * 8;
            int gr  = r0 + m;
            uint4 vh = make_uint4(0u, 0u, 0u, 0u);
            uint4 vl = make_uint4(0u, 0u, 0u, 0u);
            if (gr < N) {
                vh = __ldg(reinterpret_cast<const uint4*>(gh + (size_t)gr * D + k8));
                vl = __ldg(reinterpret_cast<const uint4*>(gl + (size_t)gr * D + k8));
            }
            int o = m * ASTRIDE + k8;
            *reinterpret_cast<uint4*>(sAh + o) = vh;
            *reinterpret_cast<uint4*>(sAl + o) = vl;
        }
    };
    // x: fp32 -> split (single conversion pass per CTA)
    auto loadAx = [&]() {
        #pragma unroll
        for (int i = 0; i < (MTILE * D / 4) / THREADS; ++i) {   // 8
            int idx = tid + i * THREADS;
            int m   = idx >> 5;
            int k4  = (idx & 31) * 4;
            int gr  = r0 + m;
            float4 v = make_float4(0.f, 0.f, 0.f, 0.f);
            if (gr < N)
                v = __ldg(reinterpret_cast<const float4*>(x + (size_t)gr * D + k4));
            uint16_t h0,h1,h2,h3, l0,l1,l2,l3;
            split_bf16(v.x, h0, l0); split_bf16(v.y, h1, l1);
            split_bf16(v.z, h2, l2); split_bf16(v.w, h3, l3);
            int o = m * ASTRIDE + k4;
            *reinterpret_cast<uint2*>(sAh + o) =
                make_uint2((uint32_t)h0 | ((uint32_t)h1 << 16),
                           (uint32_t)h2 | ((uint32_t)h3 << 16));
            *reinterpret_cast<uint2*>(sAl + o) =
                make_uint2((uint32_t)l0 | ((uint32_t)l1 << 16),
                           (uint32_t)l2 | ((uint32_t)l3 << 16));
        }
    };
    auto loadB = [&](int chunk) {
        const uint4* gh = g_wt_hi + chunk * (128 * 128 / 8);
        const uint4* gl = g_wt_lo + chunk * (128 * 128 / 8);
        #pragma unroll
        for (int i = 0; i < 8; ++i) {
            int idx = tid + i * THREADS;
            int n   = idx >> 4;
            int k8  = (idx & 15) * 8;
            int o   = n * ASTRIDE + k8;
            *reinterpret_cast<uint4*>(sBh + o) = __ldg(gh + idx);
            *reinterpret_cast<uint4*>(sBl + o) = __ldg(gl + idx);
        }
    };
    auto initBias = [&](const float* __restrict__ b) {
        #pragma unroll
        for (int nt = 0; nt < 8; ++nt) {
            float2 bv = __ldg(reinterpret_cast<const float2*>(b + wn0 + nt * 8 + 2 * t4));
            c[nt][0] = bv.x; c[nt][1] = bv.y;
            c[nt][2] = bv.x; c[nt][3] = bv.y;
        }
    };

    auto gemm = [&]() {
        #pragma unroll 1
        for (int ks = 0; ks < 8; ++ks) {
            const uint32_t kb = ks * 32;
            uint32_t aH[4], aL[4], bH[8][2], bL[8][2];
            ldsm_x4(aH[0], aH[1], aH[2], aH[3], aBaseH + kb);
            ldsm_x4(aL[0], aL[1], aL[2], aL[3], aBaseL + kb);
            #pragma unroll
            for (int np = 0; np < 4; ++np) {
                uint32_t off = (uint32_t)(np * 16 * ROWB) + kb;
                ldsm_x4(bH[2*np][0], bH[2*np][1], bH[2*np+1][0], bH[2*np+1][1],
                        bBaseH + off);
                ldsm_x4(bL[2*np][0], bL[2*np][1], bL[2*np+1][0], bL[2*np+1][1],
                        bBaseL + off);
            }
            #pragma unroll
            for (int nt = 0; nt < 8; ++nt) {
                mma16816(c[nt], aH, bH[nt]);   // hi*hi
                mma16816(c[nt], aH, bL[nt]);   // hi*lo
                mma16816(c[nt], aL, bH[nt]);   // lo*hi
            }
        }
    };

    auto epi_to_A = [&]() {
        #pragma unroll
        for (int nt = 0; nt < 8; ++nt) {
            int col = wn0 + nt * 8 + 2 * t4;
            #pragma unroll
            for (int half = 0; half < 2; ++half) {
                int row = wr0 + gid + half * 8;
                float t0 = tanhf(c[nt][half * 2 + 0]);
                float t1 = tanhf(c[nt][half * 2 + 1]);
                uint16_t h0, l0, h1, l1;
                split_bf16(t0, h0, l0); split_bf16(t1, h1, l1);
                int o = row * ASTRIDE + col;
                *reinterpret_cast<uint32_t*>(sAh + o) = (uint32_t)h0 | ((uint32_t)h1 << 16);
                *reinterpret_cast<uint32_t*>(sAl + o) = (uint32_t)l0 | ((uint32_t)l1 << 16);
            }
        }
    };

    // ====================== Layer 1: [mi, mo, x] @ W1 ======================
    initBias(b1);
    #pragma unroll 1
    for (int p = 0; p < 3; ++p) {
        if (p == 0)      copyA(g_mih, g_mil);
        else if (p == 1) copyA(g_moh, g_mol);
        else             loadAx();
        loadB(p);
        __syncthreads();
        gemm();
        __syncthreads();               // gemm reads done before next writes
    }
    epi_to_A();

    // ====================== Layers 2..4 ====================================
    const float* bs[3] = { b2, b3, b4 };
    #pragma unroll 1
    for (int l = 0; l < 3; ++l) {
        loadB(3 + l);                  // sB free (post-gemm sync above)
        __syncthreads();               // epi sA writes + loadB visible
        initBias(bs[l]);
        gemm();
        __syncthreads();               // gemm reads done
        if (l < 2) {
            epi_to_A();
        } else {
            float* sOut = reinterpret_cast<float*>(smem + OFF_B_HI);  // [64][132]
            #pragma unroll
            for (int nt = 0; nt < 8; ++nt) {
                int col = wn0 + nt * 8 + 2 * t4;
                #pragma unroll
                for (int half = 0; half < 2; ++half) {
                    int row = wr0 + gid + half * 8;
                    float2 v;
                    v.x = tanhf(c[nt][half * 2 + 0]);
                    v.y = tanhf(c[nt][half * 2 + 1]);
                    *reinterpret_cast<float2*>(sOut + row * 132 + col) = v;
                }
            }
            __syncthreads();
            #pragma unroll
            for (int i = 0; i < (MTILE * D / 4) / THREADS; ++i) {   // 8
                int idx = tid + i * THREADS;
                int m   = idx >> 5;
                int c4  = (idx & 31) * 4;
                int gr  = r0 + m;
                if (gr < N)
                    *reinterpret_cast<float4*>(out + (size_t)gr * D + c4) =
                        *reinterpret_cast<const float4*>(sOut + m * 132 + c4);
            }
        }
    }
}

// ---------------------------------------------------------------------------
// Host launcher (graph-capturable: kernel launches only)
// ---------------------------------------------------------------------------
extern "C" void kernel_launch(void* const* d_in, const int* in_sizes, int n_in,
                              void* d_out, int out_size) {
    const float* x    = (const float*)d_in[0];
    const float* ew   = (const float*)d_in[1];
    const void*  eidx = d_in[2];
    const float* W1   = (const float*)d_in[3];
    const float* b1   = (const float*)d_in[4];
    const float* W2   = (const float*)d_in[5];
    const float* b2   = (const float*)d_in[6];
    const float* W3   = (const float*)d_in[7];
    const float* b3   = (const float*)d_in[8];
    const float* W4   = (const float*)d_in[9];
    const float* b4   = (const float*)d_in[10];
    float*       out  = (float*)d_out;

    const int N = in_sizes[0] / D;        // 50000
    const int E = in_sizes[2] / 2;        // 800000

    // ---- incidence CSR build (zero_deg also detects index dtype) ----
    zero_deg_kernel<<<(N + 255) / 256, 256>>>(eidx, E, N);
    hist_kernel<<<(E + 255) / 256, 256>>>(eidx, E, N);
    {
        int nblk = (N + SCAN_B - 1) / SCAN_B;          // 49
        scan_block_kernel<<<nblk, SCAN_B>>>(N);
        scan_tops_kernel<<<1, 64>>>(nblk);
        scan_add_kernel<<<nblk, SCAN_B>>>(N);
    }
    fill_kernel<<<(E + 255) / 256, 256>>>(eidx, ew, E, N);

    // ---- weight prep ----
    {
        int total = 6 * 128 * 128;
        prep_w_kernel<<<(total + 255) / 256, 256>>>(W1, W2, W3, W4);
    }

    // ---- atomic-free aggregation (emits pre-split bf16) ----
    aggregate_kernel<<<(N + 7) / 8, 256>>>(x, N);

    // ---- fused MLP (mma.sync bf16-split + ldmatrix, MTILE=64) ----
    {
        cudaFuncSetAttribute(mlp_mma_kernel,
                             cudaFuncAttributeMaxDynamicSharedMemorySize, SMEM_TOTAL);
        int blocks = (N + MTILE - 1) / MTILE;       // 782
        mlp_mma_kernel<<<blocks, THREADS, SMEM_TOTAL>>>(x, b1, b2, b3, b4, out, N);
    }
}